// round 2
// baseline (speedup 1.0000x reference)
#include <cuda_runtime.h>
#include <cstdint>

// Problem geometry
#define T_DIM   4096
#define D_DIM   6144
#define NT0     3072        // T - TD_MAX
#define TD_MAXL 1024

// Correlation tiling
#define CB      64          // columns per block (2 per thread, packed f32x2)
#define BI      64          // i-rows per block
#define LPW     16          // lags per warp
#define NWARP   8
#define LPB     (LPW*NWARP) // 128 lags per block
#define NCB     (D_DIM/CB)      // 96
#define NIB     (NT0/BI)        // 48
#define NLB     (TD_MAXL/LPB)   // 8
#define NPART   (NCB*NIB)       // 4608 partials per lag
#define SH_ROWS (BI+LPB)        // 192 rows in shift tile
#define SMEM_BYTES ((BI + SH_ROWS) * CB * 4)   // 65536

typedef unsigned long long ull;

// Scratch (device globals — no runtime allocation)
__device__ float g_S2[T_DIM];
__device__ float g_partial[(size_t)TD_MAXL * NPART];

#define FFMA2(acc, a, b) \
    asm("fma.rn.f32x2 %0, %1, %2, %0;" : "+l"(acc) : "l"(a), "l"(b))

// ---------------------------------------------------------------------------
// Kernel 1: per-row sum of squares  S2[t] = sum_j x[t][j]^2
// ---------------------------------------------------------------------------
__global__ void __launch_bounds__(256) s2_kernel(const float* __restrict__ x) {
    int t = blockIdx.x;
    const float4* row = (const float4*)(x + (size_t)t * D_DIM);
    float s = 0.f;
    for (int j = threadIdx.x; j < D_DIM / 4; j += 256) {
        float4 v = row[j];
        s += v.x * v.x + v.y * v.y + v.z * v.z + v.w * v.w;
    }
    __shared__ float red[256];
    red[threadIdx.x] = s;
    __syncthreads();
    for (int o = 128; o; o >>= 1) {
        if (threadIdx.x < o) red[threadIdx.x] += red[threadIdx.x + o];
        __syncthreads();
    }
    if (threadIdx.x == 0) g_S2[t] = red[0];
}

// ---------------------------------------------------------------------------
// Kernel 2: banded cross-correlation partials
//   C[td] = sum_{i<3072} sum_j x[i+td][j] * x[i][j]
// Block (cb, lb, ib): 64 cols, 128 lags, 64 i-rows. Thread = 2 packed cols,
// 16 lags via rotating register window. FFMA2 packed math.
// ---------------------------------------------------------------------------
__global__ void __launch_bounds__(256) corr_kernel(const float* __restrict__ x) {
    extern __shared__ float sm[];
    float* base_s  = sm;                 // BI x 64
    float* shift_s = sm + BI * CB;       // SH_ROWS x 64

    const int cb = blockIdx.x, lb = blockIdx.y, ib = blockIdx.z;
    const int c0  = cb * CB;
    const int i0  = ib * BI;
    const int td0 = lb * LPB;
    const int tid = threadIdx.x;

    // Load base tile: rows [i0, i0+BI), 16 float4 per row
    for (int p = tid; p < BI * 16; p += 256) {
        int r = p >> 4, q = p & 15;
        ((float4*)base_s)[p] =
            ((const float4*)(x + (size_t)(i0 + r) * D_DIM + c0))[q];
    }
    // Load shift tile: rows [i0+td0, i0+td0+SH_ROWS)
    {
        int r0 = i0 + td0;
        for (int p = tid; p < SH_ROWS * 16; p += 256) {
            int r = p >> 4, q = p & 15;
            ((float4*)shift_s)[p] =
                ((const float4*)(x + (size_t)(r0 + r) * D_DIM + c0))[q];
        }
    }
    __syncthreads();

    const int wid = tid >> 5, ln = tid & 31;
    const ull* b2 = (const ull*)base_s;   // row stride 32 ull
    const ull* s2 = (const ull*)shift_s;
    const int sbase = wid * LPW;          // this warp's lag offset in rows

    ull acc[LPW];
#pragma unroll
    for (int k = 0; k < LPW; k++) acc[k] = 0ull;   // (0.f, 0.f)

    ull win[LPW];
#pragma unroll
    for (int k = 0; k < LPW; k++) win[k] = s2[(sbase + k) * 32 + ln];

    for (int i = 0; i < BI; i += LPW) {
#pragma unroll
        for (int u = 0; u < LPW; u++) {
            ull b = b2[(i + u) * 32 + ln];
#pragma unroll
            for (int k = 0; k < LPW; k++)
                FFMA2(acc[k], b, win[(u + k) & (LPW - 1)]);
            // advance window: bring in shift[(i+u) + sbase + 16]
            win[u] = s2[(sbase + i + u + LPW) * 32 + ln];
        }
    }

    // Reduce: packed halves, then across the 32 lanes (64 columns total)
#pragma unroll
    for (int k = 0; k < LPW; k++) {
        float v = __uint_as_float((unsigned)acc[k]) +
                  __uint_as_float((unsigned)(acc[k] >> 32));
#pragma unroll
        for (int o = 16; o; o >>= 1)
            v += __shfl_down_sync(0xFFFFFFFFu, v, o);
        if (ln == 0) {
            int td = td0 + wid * LPW + k;
            g_partial[(size_t)td * NPART + cb * NIB + ib] = v;
        }
    }
}

// ---------------------------------------------------------------------------
// Kernel 3: finalize. One block per td: reduce 4608 partials -> C[td],
// both S2 windows -> A[td], A[0], combine in fp64.
// ---------------------------------------------------------------------------
__global__ void __launch_bounds__(256) finalize_kernel(float* __restrict__ out) {
    const int td = blockIdx.x;
    const int tid = threadIdx.x;

    double c = 0.0;
    const float* p = g_partial + (size_t)td * NPART;
    for (int j = tid; j < NPART; j += 256) c += (double)p[j];

    double a = 0.0, a0 = 0.0;
    for (int j = tid; j < NT0; j += 256) {
        a  += (double)g_S2[td + j];
        a0 += (double)g_S2[j];
    }

    double part = a + a0 - 2.0 * c;
    __shared__ double red[256];
    red[tid] = part;
    __syncthreads();
    for (int o = 128; o; o >>= 1) {
        if (tid < o) red[tid] += red[tid + o];
        __syncthreads();
    }
    if (tid == 0) {
        const double invN = 1.0 / ((double)NT0 * (double)D_DIM);
        out[td] = (td == 0) ? 0.0f : (float)(red[0] * invN);
    }
}

// ---------------------------------------------------------------------------
extern "C" void kernel_launch(void* const* d_in, const int* in_sizes, int n_in,
                              void* d_out, int out_size) {
    (void)in_sizes; (void)n_in; (void)out_size;
    const float* x = (const float*)d_in[0];
    float* out = (float*)d_out;

    static bool attr_set = false;
    if (!attr_set) {
        cudaFuncSetAttribute(corr_kernel,
                             cudaFuncAttributeMaxDynamicSharedMemorySize,
                             SMEM_BYTES);
        attr_set = true;
    }

    s2_kernel<<<T_DIM, 256>>>(x);
    corr_kernel<<<dim3(NCB, NLB, NIB), 256, SMEM_BYTES>>>(x);
    finalize_kernel<<<TD_MAXL, 256>>>(out);
}

// round 6
// speedup vs baseline: 5.0258x; 5.0258x over previous
#include <cuda_runtime.h>
#include <cuda_bf16.h>
#include <cstdint>

// ---------------- geometry ----------------
#define T_DIM   4096
#define D_DIM   6144
#define NT0     3072
#define TDM     1024

// ---------------- tiling ------------------
#define KCH     64                   // bf16 K per chunk (128B row)
#define NCHUNK  48                   // chunks per K-half (3072/64)
#define NST     3                    // pipeline stages
#define TILE_B  16384                // 128 rows x 128 B
#define STAGE_B (2*TILE_B)           // A(shift) + B(base)
#define SMEM_DYN (NST*STAGE_B)       // 98304
#define NN0     24
#define NQQ     9
#define NTILE   (NN0*NQQ)            // 216

typedef unsigned int u32;

// ---------------- scratch (device globals) --------------
__device__ __nv_bfloat16 g_xbf[(size_t)T_DIM * D_DIM];   // 48 MB
__device__ float g_S2[T_DIM];
__device__ float g_diag[2 * NTILE * 256];

// ---------------- PTX helpers ----------------
__device__ __forceinline__ u32 smem_u32(const void* p) {
    u32 a;
    asm("{ .reg .u64 t; cvta.to.shared.u64 t, %1; cvt.u32.u64 %0, t; }"
        : "=r"(a) : "l"(p));
    return a;
}
#define CP_COMMIT()  asm volatile("cp.async.commit_group;" ::: "memory")
#define CP_WAIT(n)   asm volatile("cp.async.wait_group %0;" :: "n"(n) : "memory")

#define LDSM4(r, addr) \
    asm volatile("ldmatrix.sync.aligned.m8n8.x4.shared.b16 {%0,%1,%2,%3}, [%4];" \
        : "=r"((r)[0]), "=r"((r)[1]), "=r"((r)[2]), "=r"((r)[3]) : "r"(addr))

#define MMA16816(c, a, b0, b1) \
    asm volatile("mma.sync.aligned.m16n8k16.row.col.f32.bf16.bf16.f32 " \
        "{%0,%1,%2,%3}, {%4,%5,%6,%7}, {%8,%9}, {%0,%1,%2,%3};" \
        : "+f"((c)[0]), "+f"((c)[1]), "+f"((c)[2]), "+f"((c)[3]) \
        : "r"((a)[0]), "r"((a)[1]), "r"((a)[2]), "r"((a)[3]), "r"(b0), "r"(b1))

// ---------------------------------------------------------------------------
// Kernel 1: fp32 -> bf16 convert + exact per-row sum of squares
// ---------------------------------------------------------------------------
__global__ void __launch_bounds__(256) s2cvt_kernel(const float* __restrict__ x) {
    int t = blockIdx.x;
    const float4* row = (const float4*)(x + (size_t)t * D_DIM);
    uint2* orow = (uint2*)(g_xbf + (size_t)t * D_DIM);
    float s = 0.f;
    for (int j = threadIdx.x; j < D_DIM / 4; j += 256) {
        float4 v = row[j];
        s += v.x * v.x + v.y * v.y + v.z * v.z + v.w * v.w;
        __nv_bfloat162 lo = __floats2bfloat162_rn(v.x, v.y);
        __nv_bfloat162 hi = __floats2bfloat162_rn(v.z, v.w);
        uint2 w;
        w.x = *(u32*)&lo;
        w.y = *(u32*)&hi;
        orow[j] = w;
    }
    __shared__ float red[256];
    red[threadIdx.x] = s;
    __syncthreads();
    for (int o = 128; o; o >>= 1) {
        if (threadIdx.x < o) red[threadIdx.x] += red[threadIdx.x + o];
        __syncthreads();
    }
    if (threadIdx.x == 0) g_S2[t] = red[0];
}

// ---------------------------------------------------------------------------
// Kernel 2: banded Gram matrix via mma.sync bf16 (HMMA).
// CTA (n0, qq, z): tile G[r][c] = <x[(n0+qq)*128+r], x[n0*128+c]> over
// K-half z. 8 warps, each 64x32 output, register accumulators.
// ---------------------------------------------------------------------------
__device__ __forceinline__ void load_chunk(u32 stage, int kbase,
                                           int brow, int arow, int tid) {
    const __nv_bfloat16* xp = g_xbf + kbase;
#pragma unroll
    for (int it = 0; it < 8; it++) {
        int p = tid + it * 256;
        int t = p >> 10;                  // 0 = A (shift rows), 1 = B (base)
        int r = (p >> 3) & 127;
        int u = p & 7;
        int grow = (t ? brow : arow) + r;
        const void* src = xp + (size_t)grow * D_DIM + (u << 3);
        u32 dst = stage + (t << 14) +
                  (((u32)(r * 128 + u * 16)) ^ (((u32)(r & 7)) << 4));
        asm volatile("cp.async.cg.shared.global [%0], [%1], 16;"
                     :: "r"(dst), "l"(src) : "memory");
    }
}

__global__ void __launch_bounds__(256, 2) corr_kernel() {
    extern __shared__ __align__(1024) char smem[];
    const u32 sb = smem_u32(smem);
    const int tid = threadIdx.x, l = tid & 31, wid = tid >> 5;
    const int warp_m = wid >> 2, warp_n = wid & 3;
    const int n0 = blockIdx.x, qq = blockIdx.y, z = blockIdx.z;
    const int brow = n0 << 7;
    const int arow = (n0 + qq) << 7;
    const int kbase = z * 3072;

    float c[4][4][4];
#pragma unroll
    for (int i = 0; i < 4; i++)
#pragma unroll
        for (int j = 0; j < 4; j++)
#pragma unroll
            for (int k = 0; k < 4; k++) c[i][j][k] = 0.f;

    // Unswizzled per-lane base offsets; swizzle XOR applied LAST at each
    // ldmatrix (swz depends only on row&7, invariant under all offsets).
    const int a_row = warp_m * 64 + ((l >> 3) & 1) * 8 + (l & 7);
    const u32 a_off = (u32)(a_row * 128 + (l >> 4) * 16);
    const u32 a_swz = ((u32)(a_row & 7)) << 4;
    const int b_row = warp_n * 32 + (l & 7);
    const u32 b_off = (u32)(b_row * 128 + (l >> 3) * 16);
    const u32 b_swz = ((u32)(b_row & 7)) << 4;

    // Prologue: 2 stages in flight
    for (int s = 0; s < 2; s++) {
        load_chunk(sb + s * STAGE_B, kbase + s * KCH, brow, arow, tid);
        CP_COMMIT();
    }

    int sidx = 0;
    for (int ch = 0; ch < NCHUNK; ch++) {
        CP_WAIT(1);
        __syncthreads();
        const u32 Ab = sb + sidx * STAGE_B + a_off;
        const u32 Bb = sb + sidx * STAGE_B + TILE_B + b_off;
#pragma unroll
        for (int kd = 0; kd < 2; kd++) {
            u32 bq[4][4];
#pragma unroll
            for (int ni = 0; ni < 4; ni++)
                LDSM4(bq[ni], (Bb + ni * 1024 + kd * 64) ^ b_swz);
#pragma unroll
            for (int h = 0; h < 2; h++) {
                u32 aq[4][4];
#pragma unroll
                for (int mi = 0; mi < 4; mi++)
                    LDSM4(aq[mi], (Ab + mi * 2048 + (kd * 2 + h) * 32) ^ a_swz);
#pragma unroll
                for (int mi = 0; mi < 4; mi++)
#pragma unroll
                    for (int ni = 0; ni < 4; ni++)
                        MMA16816(c[mi][ni], aq[mi],
                                 bq[ni][2 * h], bq[ni][2 * h + 1]);
            }
        }
        int cn = ch + 2;
        if (cn < NCHUNK) {
            int sn = sidx + 2; if (sn >= NST) sn -= NST;
            load_chunk(sb + sn * STAGE_B, kbase + cn * KCH, brow, arow, tid);
        }
        CP_COMMIT();
        if (++sidx == NST) sidx = 0;
    }

    // Epilogue: regs -> smem G (pitch 129) -> diagonal sums
    __syncthreads();
    float* G = (float*)smem;
#pragma unroll
    for (int mi = 0; mi < 4; mi++)
#pragma unroll
        for (int ni = 0; ni < 4; ni++) {
            int r0 = warp_m * 64 + mi * 16 + (l >> 2);
            int c0 = warp_n * 32 + ni * 8 + ((l & 3) << 1);
            G[r0 * 129 + c0]           = c[mi][ni][0];
            G[r0 * 129 + c0 + 1]       = c[mi][ni][1];
            G[(r0 + 8) * 129 + c0]     = c[mi][ni][2];
            G[(r0 + 8) * 129 + c0 + 1] = c[mi][ni][3];
        }
    __syncthreads();

    if (tid < 255) {
        int d = tid - 127;              // td = 128*qq + d
        float s = 0.f;
        for (int rr = 0; rr < 128; rr++) {
            int cc = rr - d;
            if ((unsigned)cc < 128u) s += G[rr * 129 + cc];
        }
        g_diag[((size_t)(z * NTILE + n0 * NQQ + qq)) * 256 + tid] = s;
    }
}

// ---------------------------------------------------------------------------
// Kernel 3: finalize. msd[td] = (A[td] + A[0] - 2*C[td]) / (NT0*D)
// ---------------------------------------------------------------------------
__global__ void __launch_bounds__(256) finalize_kernel(float* __restrict__ out) {
    const int td = blockIdx.x, tid = threadIdx.x;
    const int qq = td >> 7, d1 = td & 127;

    double c = 0.0;
    if (tid < 48) {
        int n = tid >> 1, zz = tid & 1;
        c = (double)g_diag[((size_t)(zz * NTILE + n * NQQ + qq)) * 256 + 127 + d1];
        if (d1)
            c += (double)g_diag[((size_t)(zz * NTILE + n * NQQ + qq + 1)) * 256 + d1 - 1];
    }

    double a = 0.0, a0 = 0.0;
    for (int j = tid; j < NT0; j += 256) {
        a  += (double)g_S2[td + j];
        a0 += (double)g_S2[j];
    }

    double part = a + a0 - 2.0 * c;
    __shared__ double red[256];
    red[tid] = part;
    __syncthreads();
    for (int o = 128; o; o >>= 1) {
        if (tid < o) red[tid] += red[tid + o];
        __syncthreads();
    }
    if (tid == 0) {
        const double invN = 1.0 / ((double)NT0 * (double)D_DIM);
        out[td] = (td == 0) ? 0.0f : (float)(red[0] * invN);
    }
}

// ---------------------------------------------------------------------------
extern "C" void kernel_launch(void* const* d_in, const int* in_sizes, int n_in,
                              void* d_out, int out_size) {
    (void)in_sizes; (void)n_in; (void)out_size;
    const float* x = (const float*)d_in[0];
    float* out = (float*)d_out;

    static bool attr_set = false;
    if (!attr_set) {
        cudaFuncSetAttribute(corr_kernel,
                             cudaFuncAttributeMaxDynamicSharedMemorySize,
                             SMEM_DYN);
        attr_set = true;
    }

    s2cvt_kernel<<<T_DIM, 256>>>(x);
    corr_kernel<<<dim3(NN0, NQQ, 2), 256, SMEM_DYN>>>();
    finalize_kernel<<<TDM, 256>>>(out);
}

// round 7
// speedup vs baseline: 5.0811x; 1.0110x over previous
#include <cuda_runtime.h>
#include <cuda_bf16.h>
#include <cstdint>

// ---------------- geometry ----------------
#define T_DIM   4096
#define D_DIM   6144
#define NT0     3072
#define TDM     1024

// ---------------- tiling ------------------
#define KCH     64                   // bf16 K per chunk (128B row)
#define NZ      4                    // K splits
#define KSPLIT  (D_DIM/NZ)           // 1536
#define NCHUNK  (KSPLIT/KCH)         // 24 chunks per K-quarter
#define NST     3                    // pipeline stages
#define TILE_B  16384                // 128 rows x 128 B
#define STAGE_B (2*TILE_B)           // A(shift) + B(base)
#define SMEM_DYN (NST*STAGE_B)       // 98304
#define NN0     24
#define NQQ     9
#define NTILE   (NN0*NQQ)            // 216

typedef unsigned int u32;

// ---------------- scratch (device globals) --------------
__device__ __nv_bfloat16 g_xbf[(size_t)T_DIM * D_DIM];   // 48 MB
__device__ float g_S2[T_DIM];
__device__ float g_diag[NZ * NTILE * 256];

// ---------------- PTX helpers ----------------
__device__ __forceinline__ u32 smem_u32(const void* p) {
    u32 a;
    asm("{ .reg .u64 t; cvta.to.shared.u64 t, %1; cvt.u32.u64 %0, t; }"
        : "=r"(a) : "l"(p));
    return a;
}
#define CP_COMMIT()  asm volatile("cp.async.commit_group;" ::: "memory")
#define CP_WAIT(n)   asm volatile("cp.async.wait_group %0;" :: "n"(n) : "memory")

#define LDSM4(r, addr) \
    asm volatile("ldmatrix.sync.aligned.m8n8.x4.shared.b16 {%0,%1,%2,%3}, [%4];" \
        : "=r"((r)[0]), "=r"((r)[1]), "=r"((r)[2]), "=r"((r)[3]) : "r"(addr))

#define MMA16816(c, a, b0, b1) \
    asm volatile("mma.sync.aligned.m16n8k16.row.col.f32.bf16.bf16.f32 " \
        "{%0,%1,%2,%3}, {%4,%5,%6,%7}, {%8,%9}, {%0,%1,%2,%3};" \
        : "+f"((c)[0]), "+f"((c)[1]), "+f"((c)[2]), "+f"((c)[3]) \
        : "r"((a)[0]), "r"((a)[1]), "r"((a)[2]), "r"((a)[3]), "r"(b0), "r"(b1))

// ---------------------------------------------------------------------------
// Kernel 1: fp32 -> bf16 convert + exact per-row sum of squares
// ---------------------------------------------------------------------------
__global__ void __launch_bounds__(256) s2cvt_kernel(const float* __restrict__ x) {
    int t = blockIdx.x;
    const float4* row = (const float4*)(x + (size_t)t * D_DIM);
    uint4* orow = (uint4*)(g_xbf + (size_t)t * D_DIM);
    float s = 0.f;
    for (int j = threadIdx.x; j < D_DIM / 8; j += 256) {
        float4 v0 = row[2 * j];
        float4 v1 = row[2 * j + 1];
        s += v0.x * v0.x + v0.y * v0.y + v0.z * v0.z + v0.w * v0.w;
        s += v1.x * v1.x + v1.y * v1.y + v1.z * v1.z + v1.w * v1.w;
        __nv_bfloat162 p0 = __floats2bfloat162_rn(v0.x, v0.y);
        __nv_bfloat162 p1 = __floats2bfloat162_rn(v0.z, v0.w);
        __nv_bfloat162 p2 = __floats2bfloat162_rn(v1.x, v1.y);
        __nv_bfloat162 p3 = __floats2bfloat162_rn(v1.z, v1.w);
        uint4 w;
        w.x = *(u32*)&p0; w.y = *(u32*)&p1;
        w.z = *(u32*)&p2; w.w = *(u32*)&p3;
        orow[j] = w;
    }
    __shared__ float red[256];
    red[threadIdx.x] = s;
    __syncthreads();
    for (int o = 128; o; o >>= 1) {
        if (threadIdx.x < o) red[threadIdx.x] += red[threadIdx.x + o];
        __syncthreads();
    }
    if (threadIdx.x == 0) g_S2[t] = red[0];
}

// ---------------------------------------------------------------------------
// Kernel 2: banded Gram matrix via mma.sync bf16 (HMMA).
// CTA (n0, qq, z): tile G[r][c] = <x[(n0+qq)*128+r], x[n0*128+c]> over
// K-quarter z. 8 warps, each 64x32 output, register accumulators.
// ---------------------------------------------------------------------------
__device__ __forceinline__ void load_chunk(u32 stage, int kbase,
                                           int brow, int arow, int tid) {
    const __nv_bfloat16* xp = g_xbf + kbase;
#pragma unroll
    for (int it = 0; it < 8; it++) {
        int p = tid + it * 256;
        int t = p >> 10;                  // 0 = A (shift rows), 1 = B (base)
        int r = (p >> 3) & 127;
        int u = p & 7;
        int grow = (t ? brow : arow) + r;
        const void* src = xp + (size_t)grow * D_DIM + (u << 3);
        u32 dst = stage + (t << 14) +
                  (((u32)(r * 128 + u * 16)) ^ (((u32)(r & 7)) << 4));
        asm volatile("cp.async.cg.shared.global [%0], [%1], 16;"
                     :: "r"(dst), "l"(src) : "memory");
    }
}

__global__ void __launch_bounds__(256, 2) corr_kernel() {
    extern __shared__ __align__(1024) char smem[];
    const u32 sb = smem_u32(smem);
    const int tid = threadIdx.x, l = tid & 31, wid = tid >> 5;
    const int warp_m = wid >> 2, warp_n = wid & 3;
    const int n0 = blockIdx.x, qq = blockIdx.y, z = blockIdx.z;
    const int brow = n0 << 7;
    const int arow = (n0 + qq) << 7;
    const int kbase = z * KSPLIT;

    float c[4][4][4];
#pragma unroll
    for (int i = 0; i < 4; i++)
#pragma unroll
        for (int j = 0; j < 4; j++)
#pragma unroll
            for (int k = 0; k < 4; k++) c[i][j][k] = 0.f;

    // Unswizzled per-lane base offsets; swizzle XOR applied LAST at each
    // ldmatrix (swz depends only on row&7, invariant under all offsets).
    const int a_row = warp_m * 64 + ((l >> 3) & 1) * 8 + (l & 7);
    const u32 a_off = (u32)(a_row * 128 + (l >> 4) * 16);
    const u32 a_swz = ((u32)(a_row & 7)) << 4;
    const int b_row = warp_n * 32 + (l & 7);
    const u32 b_off = (u32)(b_row * 128 + (l >> 3) * 16);
    const u32 b_swz = ((u32)(b_row & 7)) << 4;

    // Prologue: 2 stages in flight
    for (int s = 0; s < 2; s++) {
        load_chunk(sb + s * STAGE_B, kbase + s * KCH, brow, arow, tid);
        CP_COMMIT();
    }

    int sidx = 0;
    for (int ch = 0; ch < NCHUNK; ch++) {
        CP_WAIT(1);
        __syncthreads();
        const u32 Ab = sb + sidx * STAGE_B + a_off;
        const u32 Bb = sb + sidx * STAGE_B + TILE_B + b_off;
#pragma unroll
        for (int kd = 0; kd < 2; kd++) {
            u32 bq[4][4];
#pragma unroll
            for (int ni = 0; ni < 4; ni++)
                LDSM4(bq[ni], (Bb + ni * 1024 + kd * 64) ^ b_swz);
#pragma unroll
            for (int h = 0; h < 2; h++) {
                u32 aq[4][4];
#pragma unroll
                for (int mi = 0; mi < 4; mi++)
                    LDSM4(aq[mi], (Ab + mi * 2048 + (kd * 2 + h) * 32) ^ a_swz);
#pragma unroll
                for (int mi = 0; mi < 4; mi++)
#pragma unroll
                    for (int ni = 0; ni < 4; ni++)
                        MMA16816(c[mi][ni], aq[mi],
                                 bq[ni][2 * h], bq[ni][2 * h + 1]);
            }
        }
        int cn = ch + 2;
        if (cn < NCHUNK) {
            int sn = sidx + 2; if (sn >= NST) sn -= NST;
            load_chunk(sb + sn * STAGE_B, kbase + cn * KCH, brow, arow, tid);
        }
        CP_COMMIT();
        if (++sidx == NST) sidx = 0;
    }

    // Epilogue: regs -> smem G (pitch 129) -> diagonal sums
    __syncthreads();
    float* G = (float*)smem;
#pragma unroll
    for (int mi = 0; mi < 4; mi++)
#pragma unroll
        for (int ni = 0; ni < 4; ni++) {
            int r0 = warp_m * 64 + mi * 16 + (l >> 2);
            int c0 = warp_n * 32 + ni * 8 + ((l & 3) << 1);
            G[r0 * 129 + c0]           = c[mi][ni][0];
            G[r0 * 129 + c0 + 1]       = c[mi][ni][1];
            G[(r0 + 8) * 129 + c0]     = c[mi][ni][2];
            G[(r0 + 8) * 129 + c0 + 1] = c[mi][ni][3];
        }
    __syncthreads();

    if (tid < 255) {
        int d = tid - 127;              // td = 128*qq + d
        float s = 0.f;
        for (int rr = 0; rr < 128; rr++) {
            int cc = rr - d;
            if ((unsigned)cc < 128u) s += G[rr * 129 + cc];
        }
        g_diag[((size_t)(z * NTILE + n0 * NQQ + qq)) * 256 + tid] = s;
    }
}

// ---------------------------------------------------------------------------
// Kernel 3: finalize. msd[td] = (A[td] + A[0] - 2*C[td]) / (NT0*D)
// ---------------------------------------------------------------------------
__global__ void __launch_bounds__(256) finalize_kernel(float* __restrict__ out) {
    const int td = blockIdx.x, tid = threadIdx.x;
    const int qq = td >> 7, d1 = td & 127;

    double c = 0.0;
    if (tid < NN0 * NZ) {
        int n = tid >> 2, zz = tid & 3;
        c = (double)g_diag[((size_t)(zz * NTILE + n * NQQ + qq)) * 256 + 127 + d1];
        if (d1)
            c += (double)g_diag[((size_t)(zz * NTILE + n * NQQ + qq + 1)) * 256 + d1 - 1];
    }

    double a = 0.0, a0 = 0.0;
    for (int j = tid; j < NT0; j += 256) {
        a  += (double)g_S2[td + j];
        a0 += (double)g_S2[j];
    }

    double part = a + a0 - 2.0 * c;
    __shared__ double red[256];
    red[tid] = part;
    __syncthreads();
    for (int o = 128; o; o >>= 1) {
        if (tid < o) red[tid] += red[tid + o];
        __syncthreads();
    }
    if (tid == 0) {
        const double invN = 1.0 / ((double)NT0 * (double)D_DIM);
        out[td] = (td == 0) ? 0.0f : (float)(red[0] * invN);
    }
}

// ---------------------------------------------------------------------------
extern "C" void kernel_launch(void* const* d_in, const int* in_sizes, int n_in,
                              void* d_out, int out_size) {
    (void)in_sizes; (void)n_in; (void)out_size;
    const float* x = (const float*)d_in[0];
    float* out = (float*)d_out;

    static bool attr_set = false;
    if (!attr_set) {
        cudaFuncSetAttribute(corr_kernel,
                             cudaFuncAttributeMaxDynamicSharedMemorySize,
                             SMEM_DYN);
        attr_set = true;
    }

    s2cvt_kernel<<<T_DIM, 256>>>(x);
    corr_kernel<<<dim3(NN0, NQQ, NZ), 256, SMEM_DYN>>>();
    finalize_kernel<<<TDM, 256>>>(out);
}